// round 1
// baseline (speedup 1.0000x reference)
#include <cuda_runtime.h>
#include <math.h>

#define D_DIM 2048
#define L_DIM 16384
#define K_TOP 32
#define EPSV  1e-5f

#define BM 128
#define BN 64
#define BK 16
#define TM 8
#define TN 4

#define N_MAX 8192

// Scratch (allocation-free rule: __device__ globals)
__device__ float g_mu[N_MAX];
__device__ float g_istd[N_MAX];
__device__ float g_val[N_MAX * K_TOP];
__device__ int   g_idx[N_MAX * K_TOP];

// ---------------------------------------------------------------------------
// Kernel 1: per-row mean & unbiased std -> mu, 1/(std+eps)
// ---------------------------------------------------------------------------
__global__ __launch_bounds__(256) void stats_kernel(const float* __restrict__ x)
{
    int n = blockIdx.x;
    const float* row = x + (size_t)n * D_DIM;
    float s = 0.f, sq = 0.f;
    for (int j = threadIdx.x; j < D_DIM; j += 256) {
        float v = row[j];
        s += v;
        sq = fmaf(v, v, sq);
    }
    __shared__ float ss[8], ssq[8];
    #pragma unroll
    for (int o = 16; o; o >>= 1) {
        s  += __shfl_down_sync(0xFFFFFFFFu, s,  o);
        sq += __shfl_down_sync(0xFFFFFFFFu, sq, o);
    }
    int w = threadIdx.x >> 5, lane = threadIdx.x & 31;
    if (lane == 0) { ss[w] = s; ssq[w] = sq; }
    __syncthreads();
    if (threadIdx.x < 32) {
        s  = (lane < 8) ? ss[lane]  : 0.f;
        sq = (lane < 8) ? ssq[lane] : 0.f;
        #pragma unroll
        for (int o = 4; o; o >>= 1) {
            s  += __shfl_down_sync(0xFFFFFFFFu, s,  o);
            sq += __shfl_down_sync(0xFFFFFFFFu, sq, o);
        }
        if (lane == 0) {
            float mu  = s / (float)D_DIM;
            float var = (sq - s * mu) / (float)(D_DIM - 1);
            var = fmaxf(var, 0.f);
            g_mu[n]   = mu;
            g_istd[n] = 1.f / (sqrtf(var) + EPSV);
        }
    }
}

// ---------------------------------------------------------------------------
// Kernel 2: latents[n, l] = dot(xn[n,:], W[l,:]) + b_enc[l]
//   xn produced on-the-fly:  (x - mu[n]) * istd[n]
//   Classic 128x64x16 SIMT tile GEMM, 8x4 per-thread microtile, 256 threads.
// ---------------------------------------------------------------------------
__global__ __launch_bounds__(256) void encode_gemm(
    const float* __restrict__ x, const float* __restrict__ W,
    const float* __restrict__ b, float* __restrict__ lat)
{
    __shared__ float As[BK][BM];
    __shared__ float Bs[BK][BN];

    const int n0  = blockIdx.y * BM;
    const int l0  = blockIdx.x * BN;
    const int tid = threadIdx.x;
    const int tx  = tid & 15;   // 0..15 -> 4 cols each (64)
    const int ty  = tid >> 4;   // 0..15 -> 8 rows each (128)

    float acc[TM][TN] = {};

    for (int d0 = 0; d0 < D_DIM; d0 += BK) {
        // ---- load A tile: 128 rows x 16 cols = 512 float4, 2 per thread ----
        #pragma unroll
        for (int r = 0; r < 2; r++) {
            int lin = tid + r * 256;
            int row = lin >> 2;
            int c4  = (lin & 3) * 4;
            float4 v = *(const float4*)&x[(size_t)(n0 + row) * D_DIM + d0 + c4];
            float mu = g_mu[n0 + row], is = g_istd[n0 + row];
            As[c4 + 0][row] = (v.x - mu) * is;
            As[c4 + 1][row] = (v.y - mu) * is;
            As[c4 + 2][row] = (v.z - mu) * is;
            As[c4 + 3][row] = (v.w - mu) * is;
        }
        // ---- load B tile: 64 rows x 16 cols = 256 float4, 1 per thread ----
        {
            int row = tid >> 2;
            int c4  = (tid & 3) * 4;
            float4 v = *(const float4*)&W[(size_t)(l0 + row) * D_DIM + d0 + c4];
            Bs[c4 + 0][row] = v.x;
            Bs[c4 + 1][row] = v.y;
            Bs[c4 + 2][row] = v.z;
            Bs[c4 + 3][row] = v.w;
        }
        __syncthreads();

        #pragma unroll
        for (int k = 0; k < BK; k++) {
            float a[TM], bb[TN];
            #pragma unroll
            for (int i = 0; i < TM; i++) a[i]  = As[k][ty * TM + i];
            #pragma unroll
            for (int j = 0; j < TN; j++) bb[j] = Bs[k][tx * TN + j];
            #pragma unroll
            for (int i = 0; i < TM; i++)
                #pragma unroll
                for (int j = 0; j < TN; j++)
                    acc[i][j] = fmaf(a[i], bb[j], acc[i][j]);
        }
        __syncthreads();
    }

    // epilogue: add bias, write latents (into the sparse-output region)
    float4 bias = *(const float4*)&b[l0 + tx * TN];
    #pragma unroll
    for (int i = 0; i < TM; i++) {
        float4 o;
        o.x = acc[i][0] + bias.x;
        o.y = acc[i][1] + bias.y;
        o.z = acc[i][2] + bias.z;
        o.w = acc[i][3] + bias.w;
        *(float4*)&lat[(size_t)(n0 + ty * TM + i) * L_DIM + l0 + tx * TN] = o;
    }
}

// ---------------------------------------------------------------------------
// Kernel 3: per-row top-32 (lowest-index tie-break), sparsify in place.
//   Row (64 KB) cached in dynamic smem; 32 x block-argmax; zero + scatter.
// ---------------------------------------------------------------------------
__global__ __launch_bounds__(256) void topk_kernel(float* __restrict__ lat)
{
    extern __shared__ float sh[];           // L_DIM floats
    __shared__ float sv[8];
    __shared__ int   si[8];
    __shared__ float selv[K_TOP];
    __shared__ int   seli[K_TOP];

    const int n   = blockIdx.x;
    const int tid = threadIdx.x;
    float* row = lat + (size_t)n * L_DIM;

    for (int j = tid; j < L_DIM; j += 256) sh[j] = row[j];
    __syncthreads();

    const float NEG = -3.4e38f;
    for (int it = 0; it < K_TOP; it++) {
        float best = NEG;
        int   bi   = L_DIM;
        for (int j = tid; j < L_DIM; j += 256) {
            float v = sh[j];
            if (v > best) { best = v; bi = j; }   // increasing j => keeps lowest idx on ties
        }
        #pragma unroll
        for (int o = 16; o; o >>= 1) {
            float ov = __shfl_down_sync(0xFFFFFFFFu, best, o);
            int   oi = __shfl_down_sync(0xFFFFFFFFu, bi,   o);
            if (ov > best || (ov == best && oi < bi)) { best = ov; bi = oi; }
        }
        int w = tid >> 5, lane = tid & 31;
        if (lane == 0) { sv[w] = best; si[w] = bi; }
        __syncthreads();
        if (tid < 32) {
            best = (lane < 8) ? sv[lane] : NEG;
            bi   = (lane < 8) ? si[lane] : L_DIM;
            #pragma unroll
            for (int o = 4; o; o >>= 1) {
                float ov = __shfl_down_sync(0xFFFFFFFFu, best, o);
                int   oi = __shfl_down_sync(0xFFFFFFFFu, bi,   o);
                if (ov > best || (ov == best && oi < bi)) { best = ov; bi = oi; }
            }
            if (lane == 0) {
                selv[it] = best;
                seli[it] = bi;
                sh[bi]   = NEG;            // remove from further consideration
            }
        }
        __syncthreads();
    }

    // zero the whole row, then scatter the 32 kept values
    for (int j = tid * 4; j < L_DIM; j += 256 * 4)
        *(float4*)&row[j] = make_float4(0.f, 0.f, 0.f, 0.f);
    __syncthreads();
    if (tid < K_TOP) {
        int   i = seli[tid];
        float v = selv[tid];
        row[i] = v;
        g_val[n * K_TOP + tid] = v;
        g_idx[n * K_TOP + tid] = i;
    }
}

// ---------------------------------------------------------------------------
// Kernel 4: recon[n,:] = pre_bias + sum_k val_k * W[idx_k, :]
// ---------------------------------------------------------------------------
__global__ __launch_bounds__(256) void decode_kernel(
    const float* __restrict__ W, const float* __restrict__ pre_bias,
    float* __restrict__ recon)
{
    __shared__ float sval[K_TOP];
    __shared__ int   sidx[K_TOP];
    const int n   = blockIdx.x;
    const int tid = threadIdx.x;
    if (tid < K_TOP) {
        sval[tid] = g_val[n * K_TOP + tid];
        sidx[tid] = g_idx[n * K_TOP + tid];
    }
    __syncthreads();

    float acc[8];
    #pragma unroll
    for (int i = 0; i < 8; i++) acc[i] = pre_bias[tid + i * 256];

    #pragma unroll 4
    for (int k = 0; k < K_TOP; k++) {
        const float* wr = W + (size_t)sidx[k] * D_DIM;
        float v = sval[k];
        #pragma unroll
        for (int i = 0; i < 8; i++)
            acc[i] = fmaf(v, wr[tid + i * 256], acc[i]);
    }
    #pragma unroll
    for (int i = 0; i < 8; i++)
        recon[(size_t)n * D_DIM + tid + i * 256] = acc[i];
}

// ---------------------------------------------------------------------------
// Launch
// ---------------------------------------------------------------------------
extern "C" void kernel_launch(void* const* d_in, const int* in_sizes, int n_in,
                              void* d_out, int out_size)
{
    const float* x  = (const float*)d_in[0];   // [N, D]
    const float* W  = (const float*)d_in[1];   // [L, D]
    const float* b  = (const float*)d_in[2];   // [L]
    const float* pb = (const float*)d_in[3];   // [D]

    const int N = in_sizes[0] / D_DIM;         // 4096

    float* recon  = (float*)d_out;                       // [N, D]
    float* sparse = recon + (size_t)N * D_DIM;           // [N, L]

    stats_kernel<<<N, 256>>>(x);

    dim3 grid(L_DIM / BN, N / BM);
    encode_gemm<<<grid, 256>>>(x, W, b, sparse);

    cudaFuncSetAttribute(topk_kernel,
                         cudaFuncAttributeMaxDynamicSharedMemorySize,
                         L_DIM * (int)sizeof(float));
    topk_kernel<<<N, 256, L_DIM * sizeof(float)>>>(sparse);

    decode_kernel<<<N, 256>>>(W, pb, recon);
}

// round 3
// speedup vs baseline: 3.6954x; 3.6954x over previous
#include <cuda_runtime.h>
#include <cuda_bf16.h>
#include <math.h>
#include <stdint.h>
#include <float.h>

#define D_DIM 2048
#define L_DIM 16384
#define K_TOP 32
#define CAP   192
#define EPSV  1e-5f
#define N_MAX 4096

// -------------------- device scratch (no allocations allowed) --------------
__device__ float g_mu[N_MAX];
__device__ float g_istd[N_MAX];
__device__ float g_val[N_MAX * K_TOP];
__device__ int   g_idx[N_MAX * K_TOP];
__device__ __nv_bfloat16 g_Xb[(size_t)N_MAX * D_DIM];   // bf16(xn)
__device__ __nv_bfloat16 g_Wb[(size_t)L_DIM * D_DIM];   // bf16(W)
__device__ __nv_bfloat16 g_lat[(size_t)N_MAX * L_DIM];  // approx latents (bf16)

// -------------------- helpers ----------------------------------------------
__device__ __forceinline__ uint32_t smem_u32(const void* p) {
    uint32_t a;
    asm("{ .reg .u64 t; cvta.to.shared.u64 t, %1; cvt.u32.u64 %0, t; }"
        : "=r"(a) : "l"(p));
    return a;
}
#define CP_ASYNC16(dst, src) \
    asm volatile("cp.async.cg.shared.global [%0], [%1], 16;" :: "r"(dst), "l"(src))
#define CP_COMMIT()  asm volatile("cp.async.commit_group;" ::: "memory")
#define CP_WAIT1()   asm volatile("cp.async.wait_group 1;" ::: "memory")

__device__ __forceinline__ void ldm_x4(uint32_t& r0, uint32_t& r1,
                                       uint32_t& r2, uint32_t& r3, uint32_t a) {
    asm volatile("ldmatrix.sync.aligned.m8n8.x4.shared.b16 {%0,%1,%2,%3}, [%4];"
                 : "=r"(r0), "=r"(r1), "=r"(r2), "=r"(r3) : "r"(a));
}
__device__ __forceinline__ void mma16816(float* c, const uint32_t* a,
                                         uint32_t b0, uint32_t b1) {
    asm volatile(
        "mma.sync.aligned.m16n8k16.row.col.f32.bf16.bf16.f32 "
        "{%0,%1,%2,%3}, {%4,%5,%6,%7}, {%8,%9}, {%0,%1,%2,%3};"
        : "+f"(c[0]), "+f"(c[1]), "+f"(c[2]), "+f"(c[3])
        : "r"(a[0]), "r"(a[1]), "r"(a[2]), "r"(a[3]), "r"(b0), "r"(b1));
}

// ---------------------------------------------------------------------------
// Kernel 1: per-row mean & unbiased std
// ---------------------------------------------------------------------------
__global__ __launch_bounds__(256) void stats_kernel(const float* __restrict__ x)
{
    int n = blockIdx.x;
    const float* row = x + (size_t)n * D_DIM;
    float s = 0.f, sq = 0.f;
    for (int j = threadIdx.x; j < D_DIM; j += 256) {
        float v = row[j];
        s += v;
        sq = fmaf(v, v, sq);
    }
    __shared__ float ss[8], ssq[8];
    #pragma unroll
    for (int o = 16; o; o >>= 1) {
        s  += __shfl_down_sync(0xFFFFFFFFu, s,  o);
        sq += __shfl_down_sync(0xFFFFFFFFu, sq, o);
    }
    int w = threadIdx.x >> 5, lane = threadIdx.x & 31;
    if (lane == 0) { ss[w] = s; ssq[w] = sq; }
    __syncthreads();
    if (threadIdx.x < 32) {
        s  = (lane < 8) ? ss[lane]  : 0.f;
        sq = (lane < 8) ? ssq[lane] : 0.f;
        #pragma unroll
        for (int o = 4; o; o >>= 1) {
            s  += __shfl_down_sync(0xFFFFFFFFu, s,  o);
            sq += __shfl_down_sync(0xFFFFFFFFu, sq, o);
        }
        if (lane == 0) {
            float mu  = s / (float)D_DIM;
            float var = (sq - s * mu) / (float)(D_DIM - 1);
            var = fmaxf(var, 0.f);
            g_mu[n]   = mu;
            g_istd[n] = 1.f / (sqrtf(var) + EPSV);
        }
    }
}

// ---------------------------------------------------------------------------
// Kernel 2a/2b: bf16 conversions
// ---------------------------------------------------------------------------
__global__ __launch_bounds__(256) void conv_x_kernel(const float* __restrict__ x)
{
    int n = blockIdx.x;
    float mu = g_mu[n], is = g_istd[n];
    const float4* src = (const float4*)(x + (size_t)n * D_DIM);
    __nv_bfloat162* dst = (__nv_bfloat162*)(g_Xb + (size_t)n * D_DIM);
    for (int t = threadIdx.x; t < D_DIM / 4; t += 256) {
        float4 v = src[t];
        __nv_bfloat162 p0, p1;
        p0.x = __float2bfloat16((v.x - mu) * is);
        p0.y = __float2bfloat16((v.y - mu) * is);
        p1.x = __float2bfloat16((v.z - mu) * is);
        p1.y = __float2bfloat16((v.w - mu) * is);
        dst[t * 2]     = p0;
        dst[t * 2 + 1] = p1;
    }
}
__global__ __launch_bounds__(256) void conv_w_kernel(const float* __restrict__ W)
{
    size_t base = (size_t)blockIdx.x * (D_DIM * 4);   // 4 rows per block
    const float4* src = (const float4*)(W + base);
    __nv_bfloat162* dst = (__nv_bfloat162*)(g_Wb + base);
    for (int t = threadIdx.x; t < D_DIM; t += 256) {  // 4*2048/4 = 2048 float4
        float4 v = src[t];
        __nv_bfloat162 p0, p1;
        p0.x = __float2bfloat16(v.x); p0.y = __float2bfloat16(v.y);
        p1.x = __float2bfloat16(v.z); p1.y = __float2bfloat16(v.w);
        dst[t * 2]     = p0;
        dst[t * 2 + 1] = p1;
    }
}

// ---------------------------------------------------------------------------
// Kernel 3: bf16 HMMA GEMM  lat[m,n] = bf16( xn_bf[m,:] . W_bf[n,:] + b[n] )
//   CTA 128x128, 8 warps (2x4), warp tile 64x32, K-stage 64, 3-stage cp.async.
// ---------------------------------------------------------------------------
#define GS_BYTES 32768            // per stage: A 16KB + B 16KB
#define G_STAGES 3
#define G_KITERS (D_DIM / 64)     // 32

__global__ __launch_bounds__(256, 2) void gemm_kernel(
    const float* __restrict__ bias)
{
    extern __shared__ char smem[];
    const uint32_t sb = smem_u32(smem);
    const int tid  = threadIdx.x;
    const int wid  = tid >> 5;
    const int lane = tid & 31;
    const int m0 = blockIdx.x * 128;           // token rows
    const int n0 = blockIdx.y * 128;           // latent cols
    const int wm = (wid & 1) * 64;
    const int wn = (wid >> 1) * 32;

    const __nv_bfloat16* Ag = g_Xb + (size_t)m0 * D_DIM;
    const __nv_bfloat16* Bg = g_Wb + (size_t)n0 * D_DIM;

    float acc[4][4][4];
    #pragma unroll
    for (int i = 0; i < 4; i++)
        #pragma unroll
        for (int j = 0; j < 4; j++)
            #pragma unroll
            for (int k = 0; k < 4; k++) acc[i][j][k] = 0.f;

    // ---- stage loader: 8 x 16B cp.async per thread ----
    const int l_row = tid >> 1;                // 0..127 (2 threads per row)
    const int l_c0  = (tid & 1) * 4;           // chunks 0-3 or 4-7
    auto load_stage = [&](int it, int sp) {
        uint32_t bA = sb + sp * GS_BYTES;
        uint32_t bB = bA + 16384;
        const __nv_bfloat16* ga = Ag + (size_t)l_row * D_DIM + it * 64 + l_c0 * 8;
        const __nv_bfloat16* gb = Bg + (size_t)l_row * D_DIM + it * 64 + l_c0 * 8;
        #pragma unroll
        for (int q = 0; q < 4; q++) {
            int c  = l_c0 + q;
            int cs = c ^ (l_row & 7);
            CP_ASYNC16(bA + l_row * 128 + cs * 16, ga + q * 8);
            CP_ASYNC16(bB + l_row * 128 + cs * 16, gb + q * 8);
        }
    };

    load_stage(0, 0); CP_COMMIT();
    load_stage(1, 1); CP_COMMIT();

    const int fr  = lane & 15;                  // fragment row
    const int fkc = lane >> 4;                  // fragment k-chunk half

    for (int it = 0; it < G_KITERS; it++) {
        CP_WAIT1();
        __syncthreads();
        int sp = it % G_STAGES;
        if (it + 2 < G_KITERS) load_stage(it + 2, (it + 2) % G_STAGES);
        CP_COMMIT();

        uint32_t bA = sb + sp * GS_BYTES;
        uint32_t bB = bA + 16384;
        #pragma unroll
        for (int kk = 0; kk < 4; kk++) {
            int ch = kk * 2 + fkc;
            uint32_t a[4][4], b[2][4];
            #pragma unroll
            for (int mt = 0; mt < 4; mt++) {
                int r = wm + mt * 16 + fr;
                ldm_x4(a[mt][0], a[mt][1], a[mt][2], a[mt][3],
                       bA + r * 128 + (ch ^ (r & 7)) * 16);
            }
            #pragma unroll
            for (int bt = 0; bt < 2; bt++) {
                int r = wn + bt * 16 + fr;
                ldm_x4(b[bt][0], b[bt][1], b[bt][2], b[bt][3],
                       bB + r * 128 + (ch ^ (r & 7)) * 16);
            }
            #pragma unroll
            for (int mt = 0; mt < 4; mt++)
                #pragma unroll
                for (int nt = 0; nt < 4; nt++) {
                    int bt = nt >> 1, sub = nt & 1;
                    mma16816(acc[mt][nt], a[mt], b[bt][sub], b[bt][sub + 2]);
                }
        }
    }

    // ---- epilogue: +bias, store bf16 pairs ----
    const int g  = lane >> 2;
    const int tg = lane & 3;
    #pragma unroll
    for (int nt = 0; nt < 4; nt++) {
        int col = n0 + wn + nt * 8 + 2 * tg;
        float b0 = bias[col], b1 = bias[col + 1];
        #pragma unroll
        for (int mt = 0; mt < 4; mt++) {
            int row = m0 + wm + mt * 16 + g;
            __nv_bfloat162 p;
            p.x = __float2bfloat16(acc[mt][nt][0] + b0);
            p.y = __float2bfloat16(acc[mt][nt][1] + b1);
            *reinterpret_cast<__nv_bfloat162*>(&g_lat[(size_t)row * L_DIM + col]) = p;
            __nv_bfloat162 q;
            q.x = __float2bfloat16(acc[mt][nt][2] + b0);
            q.y = __float2bfloat16(acc[mt][nt][3] + b1);
            *reinterpret_cast<__nv_bfloat162*>(&g_lat[(size_t)(row + 8) * L_DIM + col]) = q;
        }
    }
}

// ---------------------------------------------------------------------------
// Kernel 4: radix-select top-64 candidates on approx latents, exact fp32
//           rescore, exact top-32, zero + scatter into sparse output.
// ---------------------------------------------------------------------------
__global__ __launch_bounds__(256) void topk_kernel(
    const float* __restrict__ x, const float* __restrict__ W,
    const float* __restrict__ b, float* __restrict__ sparse)
{
    extern __shared__ char dyn[];
    uint16_t* keys = (uint16_t*)dyn;            // 32 KB
    float*    xnr  = (float*)(dyn + 32768);     // 8 KB
    __shared__ uint32_t hist[256];
    __shared__ uint32_t scan[256];
    __shared__ int   cand_idx[CAP];
    __shared__ float cand_val[CAP];
    __shared__ float selv[K_TOP];
    __shared__ int   seli[K_TOP];
    __shared__ uint32_t s_nc, s_b1, s_cab, s_T;

    const int n   = blockIdx.x;
    const int tid = threadIdx.x;
    const int lane = tid & 31;

    // ---- build 16-bit monotonic keys from bf16 approx latents ----
    const uint4* lrow = (const uint4*)(g_lat + (size_t)n * L_DIM);
    for (int j = tid; j < L_DIM / 8; j += 256) {
        uint4 v = lrow[j];
        uint32_t ws[4] = {v.x, v.y, v.z, v.w};
        #pragma unroll
        for (int q = 0; q < 4; q++) {
            uint16_t h0 = (uint16_t)(ws[q] & 0xFFFF);
            uint16_t h1 = (uint16_t)(ws[q] >> 16);
            keys[j * 8 + q * 2]     = (h0 & 0x8000) ? (uint16_t)~h0 : (uint16_t)(h0 | 0x8000);
            keys[j * 8 + q * 2 + 1] = (h1 & 0x8000) ? (uint16_t)~h1 : (uint16_t)(h1 | 0x8000);
        }
    }
    if (tid == 0) s_nc = 0;
    hist[tid] = 0;
    __syncthreads();

    // ---- pass 1: top byte ----
    for (int j = tid; j < L_DIM; j += 256)
        atomicAdd(&hist[keys[j] >> 8], 1u);
    __syncthreads();
    scan[tid] = hist[tid];
    __syncthreads();
    #pragma unroll
    for (int off = 1; off < 256; off <<= 1) {
        uint32_t add = (tid + off < 256) ? scan[tid + off] : 0;
        __syncthreads();
        scan[tid] += add;
        __syncthreads();
    }
    {
        uint32_t ge = scan[tid];
        uint32_t nx = (tid < 255) ? scan[tid + 1] : 0;
        if (ge >= 64 && nx < 64) { s_b1 = tid; s_cab = nx; }
    }
    __syncthreads();
    uint32_t b1 = s_b1, cab = s_cab;

    // ---- pass 2: low byte within bin b1 ----
    hist[tid] = 0;
    __syncthreads();
    for (int j = tid; j < L_DIM; j += 256) {
        uint16_t k = keys[j];
        if ((uint32_t)(k >> 8) == b1) atomicAdd(&hist[k & 255], 1u);
    }
    __syncthreads();
    scan[tid] = hist[tid];
    __syncthreads();
    #pragma unroll
    for (int off = 1; off < 256; off <<= 1) {
        uint32_t add = (tid + off < 256) ? scan[tid + off] : 0;
        __syncthreads();
        scan[tid] += add;
        __syncthreads();
    }
    {
        uint32_t need = 64 - cab;
        uint32_t ge = scan[tid];
        uint32_t nx = (tid < 255) ? scan[tid + 1] : 0;
        if (ge >= need && nx < need) s_T = (b1 << 8) | (uint32_t)tid;
    }
    __syncthreads();
    uint32_t T = s_T;

    // ---- pass 3: collect candidates ----
    for (int j = tid; j < L_DIM; j += 256) {
        if ((uint32_t)keys[j] >= T) {
            uint32_t p = atomicAdd(&s_nc, 1u);
            if (p < CAP) cand_idx[p] = j;
        }
    }
    // ---- build exact xn row in smem ----
    {
        float mu = g_mu[n], is = g_istd[n];
        const float4* xr = (const float4*)(x + (size_t)n * D_DIM);
        float4* xd = (float4*)xnr;
        for (int j = tid; j < D_DIM / 4; j += 256) {
            float4 v = xr[j];
            v.x = (v.x - mu) * is; v.y = (v.y - mu) * is;
            v.z = (v.z - mu) * is; v.w = (v.w - mu) * is;
            xd[j] = v;
        }
    }
    __syncthreads();
    int nc = (int)min(s_nc, (uint32_t)CAP);

    // ---- exact fp32 rescore of candidates (one warp per candidate) ----
    const float4* xv4 = (const float4*)xnr;
    for (int c = tid >> 5; c < nc; c += 8) {
        int idx = cand_idx[c];
        const float4* wr = (const float4*)(W + (size_t)idx * D_DIM);
        float s = 0.f;
        #pragma unroll
        for (int j = 0; j < 16; j++) {
            float4 wv = wr[lane + 32 * j];
            float4 xw = xv4[lane + 32 * j];
            s = fmaf(wv.x, xw.x, s);
            s = fmaf(wv.y, xw.y, s);
            s = fmaf(wv.z, xw.z, s);
            s = fmaf(wv.w, xw.w, s);
        }
        #pragma unroll
        for (int o = 16; o; o >>= 1) s += __shfl_xor_sync(0xFFFFFFFFu, s, o);
        if (lane == 0) cand_val[c] = s + b[idx];
    }
    __syncthreads();

    // ---- exact top-32 among candidates (warp 0) ----
    if (tid < 32) {
        for (int itk = 0; itk < K_TOP; itk++) {
            float bv = -FLT_MAX; int bix = 0x7FFFFFFF; int bc = -1;
            for (int c = lane; c < nc; c += 32) {
                float v = cand_val[c]; int ix = cand_idx[c];
                if (v > bv || (v == bv && ix < bix)) { bv = v; bix = ix; bc = c; }
            }
            #pragma unroll
            for (int o = 16; o; o >>= 1) {
                float ov = __shfl_down_sync(0xFFFFFFFFu, bv, o);
                int  oix = __shfl_down_sync(0xFFFFFFFFu, bix, o);
                int  oc  = __shfl_down_sync(0xFFFFFFFFu, bc, o);
                if (ov > bv || (ov == bv && oix < bix)) { bv = ov; bix = oix; bc = oc; }
            }
            if (lane == 0) {
                selv[itk] = bv;
                seli[itk] = bix;
                cand_val[bc] = -FLT_MAX;
            }
            __syncwarp();
        }
    }
    __syncthreads();

    // ---- zero sparse row, scatter exact values ----
    float4* orow = (float4*)(sparse + (size_t)n * L_DIM);
    float4 z = make_float4(0.f, 0.f, 0.f, 0.f);
    for (int j = tid; j < L_DIM / 4; j += 256) orow[j] = z;
    __syncthreads();
    if (tid < K_TOP) {
        sparse[(size_t)n * L_DIM + seli[tid]] = selv[tid];
        g_val[n * K_TOP + tid] = selv[tid];
        g_idx[n * K_TOP + tid] = seli[tid];
    }
}

// ---------------------------------------------------------------------------
// Kernel 5: recon[n,:] = pre_bias + sum_k val_k * W[idx_k, :]
// ---------------------------------------------------------------------------
__global__ __launch_bounds__(256) void decode_kernel(
    const float* __restrict__ W, const float* __restrict__ pre_bias,
    float* __restrict__ recon)
{
    __shared__ float sval[K_TOP];
    __shared__ int   sidx[K_TOP];
    const int n   = blockIdx.x;
    const int tid = threadIdx.x;
    if (tid < K_TOP) {
        sval[tid] = g_val[n * K_TOP + tid];
        sidx[tid] = g_idx[n * K_TOP + tid];
    }
    __syncthreads();

    float acc[8];
    #pragma unroll
    for (int i = 0; i < 8; i++) acc[i] = pre_bias[tid + i * 256];

    #pragma unroll 4
    for (int k = 0; k < K_TOP; k++) {
        const float* wr = W + (size_t)sidx[k] * D_DIM;
        float v = sval[k];
        #pragma unroll
        for (int i = 0; i < 8; i++)
            acc[i] = fmaf(v, wr[tid + i * 256], acc[i]);
    }
    #pragma unroll
    for (int i = 0; i < 8; i++)
        recon[(size_t)n * D_DIM + tid + i * 256] = acc[i];
}

// ---------------------------------------------------------------------------
// Launch
// ---------------------------------------------------------------------------
extern "C" void kernel_launch(void* const* d_in, const int* in_sizes, int n_in,
                              void* d_out, int out_size)
{
    const float* x  = (const float*)d_in[0];   // [N, D]
    const float* W  = (const float*)d_in[1];   // [L, D]
    const float* b  = (const float*)d_in[2];   // [L]
    const float* pb = (const float*)d_in[3];   // [D]

    const int N = in_sizes[0] / D_DIM;         // 4096

    float* recon  = (float*)d_out;             // [N, D]
    float* sparse = recon + (size_t)N * D_DIM; // [N, L]

    stats_kernel<<<N, 256>>>(x);
    conv_x_kernel<<<N, 256>>>(x);
    conv_w_kernel<<<L_DIM / 4, 256>>>(W);

    cudaFuncSetAttribute(gemm_kernel,
                         cudaFuncAttributeMaxDynamicSharedMemorySize,
                         G_STAGES * GS_BYTES);
    dim3 grid(N / 128, L_DIM / 128);
    gemm_kernel<<<grid, 256, G_STAGES * GS_BYTES>>>(b);

    topk_kernel<<<N, 256, 32768 + 8192>>>(x, W, b, sparse);

    decode_kernel<<<N, 256>>>(W, pb, recon);
}